// round 7
// baseline (speedup 1.0000x reference)
#include <cuda_runtime.h>

#define H      4096
#define TMAX   16384
#define EXP    8
#define FULLM  0xFFFFFFFFu
#define STAGES 8
#define ROWB   16384            // bytes per row stage (full 4096-float row)

// Phase-1 partials: [row][8 warps][8 experts] = 4 MB
__device__ float g_scratch[(size_t)TMAX * 8 * EXP];

typedef unsigned long long u64;

__device__ __forceinline__ u64 fma2(u64 a, u64 b, u64 c) {
    u64 d; asm("fma.rn.f32x2 %0,%1,%2,%3;" : "=l"(d) : "l"(a), "l"(b), "l"(c)); return d;
}
__device__ __forceinline__ u64 mul2(u64 a, u64 b) {
    u64 d; asm("mul.rn.f32x2 %0,%1,%2;" : "=l"(d) : "l"(a), "l"(b)); return d;
}
__device__ __forceinline__ float hadd2(u64 v) {
    float lo = __uint_as_float((unsigned)v);
    float hi = __uint_as_float((unsigned)(v >> 32));
    return lo + hi;
}
__device__ __forceinline__ void lds128(u64& a, u64& b, unsigned addr) {
    asm volatile("ld.shared.v2.u64 {%0,%1},[%2];" : "=l"(a), "=l"(b) : "r"(addr));
}
__device__ __forceinline__ void cp16(unsigned saddr, const void* gaddr) {
    asm volatile("cp.async.cg.shared.global [%0], [%1], 16;" :: "r"(saddr), "l"(gaddr));
}
__device__ __forceinline__ void cp_commit() {
    asm volatile("cp.async.commit_group;" ::: "memory");
}
__device__ __forceinline__ void cp_waitN() {
    asm volatile("cp.async.wait_group %0;" :: "n"(STAGES - 1) : "memory");
}

// Reduce 8 per-lane values across 32 lanes (vector-halving butterfly, 9 shfls).
// Result: lane 4e holds the sum for expert e.
__device__ __forceinline__ float reduce8(float a[8]) {
    const int lane = threadIdx.x & 31;
    {
        bool hi = (lane & 16) != 0;
        float s0 = hi ? a[0] : a[4];
        float s1 = hi ? a[1] : a[5];
        float s2 = hi ? a[2] : a[6];
        float s3 = hi ? a[3] : a[7];
        s0 = __shfl_xor_sync(FULLM, s0, 16);
        s1 = __shfl_xor_sync(FULLM, s1, 16);
        s2 = __shfl_xor_sync(FULLM, s2, 16);
        s3 = __shfl_xor_sync(FULLM, s3, 16);
        a[0] = (hi ? a[4] : a[0]) + s0;
        a[1] = (hi ? a[5] : a[1]) + s1;
        a[2] = (hi ? a[6] : a[2]) + s2;
        a[3] = (hi ? a[7] : a[3]) + s3;
    }
    {
        bool hi = (lane & 8) != 0;
        float s0 = hi ? a[0] : a[2];
        float s1 = hi ? a[1] : a[3];
        s0 = __shfl_xor_sync(FULLM, s0, 8);
        s1 = __shfl_xor_sync(FULLM, s1, 8);
        a[0] = (hi ? a[2] : a[0]) + s0;
        a[1] = (hi ? a[3] : a[1]) + s1;
    }
    {
        bool hi = (lane & 4) != 0;
        float s0 = hi ? a[0] : a[1];
        s0 = __shfl_xor_sync(FULLM, s0, 4);
        a[0] = (hi ? a[1] : a[0]) + s0;
    }
    float v = a[0];
    v += __shfl_xor_sync(FULLM, v, 2);
    v += __shfl_xor_sync(FULLM, v, 1);
    return v;
}

// ── Phase 1: streaming GEMV partials.
//   256 threads; thread owns 16 k (float4 in each of 4 chunks of 1024 floats).
//   W register-resident (128 regs). 8-deep per-thread cp.async pipeline into
//   private smem slots; no block sync. 8 warps → 72 shfl-instr/row/SM.
__global__ void __launch_bounds__(256, 1)
router_p1(const float* __restrict__ x, const float* __restrict__ W, int T) {
    extern __shared__ char smem[];   // STAGES * 16KB = 128KB

    const int tid  = threadIdx.x;
    const int lane = tid & 31;
    const int warp = tid >> 5;
    const int nb   = gridDim.x;

    // W regs: [chunk][expert] packed pairs = 4*8*2 u64 = 128 regs
    u64 wlo[4][EXP], whi[4][EXP];
#pragma unroll
    for (int c = 0; c < 4; c++)
#pragma unroll
        for (int e = 0; e < EXP; e++) {
            ulonglong2 t = *reinterpret_cast<const ulonglong2*>(W + e * H + c * 1024 + tid * 4);
            wlo[c][e] = t.x; whi[c][e] = t.y;
        }

    unsigned sbase;
    asm("{ .reg .u64 t; cvta.to.shared.u64 t, %1; cvt.u32.u64 %0, t; }"
        : "=r"(sbase) : "l"(smem));
    const unsigned myS = sbase + tid * 16;   // + c*4096 + s*ROWB

    const char* xg = reinterpret_cast<const char*>(x);
    const size_t myOff = (size_t)tid * 16;   // + c*4096

    const int r0 = blockIdx.x;

    // prologue: fill STAGES groups
#pragma unroll
    for (int s = 0; s < STAGES; s++) {
        int r = r0 + s * nb;
        if (r < T) {
            const char* src = xg + (size_t)r * ROWB + myOff;
#pragma unroll
            for (int c = 0; c < 4; c++)
                cp16(myS + s * ROWB + c * 4096, src + c * 4096);
        }
        cp_commit();
    }

    int s = 0;
    for (int r = r0; r < T; r += nb) {
        cp_waitN();
        __syncwarp();

        u64 xlo[4], xhi[4];
#pragma unroll
        for (int c = 0; c < 4; c++)
            lds128(xlo[c], xhi[c], myS + s * ROWB + c * 4096);

        float a8[EXP];
#pragma unroll
        for (int e = 0; e < EXP; e++) {
            u64 acc = mul2(xlo[0], wlo[0][e]);
            acc = fma2(xhi[0], whi[0][e], acc);
#pragma unroll
            for (int c = 1; c < 4; c++) {
                acc = fma2(xlo[c], wlo[c][e], acc);
                acc = fma2(xhi[c], whi[c][e], acc);
            }
            a8[e] = hadd2(acc);
        }

        float v = reduce8(a8);
        if ((lane & 3) == 0)
            g_scratch[((size_t)r * 8 + warp) * EXP + (lane >> 2)] = v;

        int rp = r + STAGES * nb;
        if (rp < T) {
            const char* src = xg + (size_t)rp * ROWB + myOff;
#pragma unroll
            for (int c = 0; c < 4; c++)
                cp16(myS + s * ROWB + c * 4096, src + c * 4096);
        }
        cp_commit();

        s = (s == STAGES - 1) ? 0 : s + 1;
    }
}

// ── Phase 2: FOUR rows per warp (octet decomposition). Lane = (row l>>3,
//   slot l&7). Butterfly over masks {4,2,1} reduces all 4 rows with 7 shfls;
//   octet lane index == expert index afterwards.
__global__ void __launch_bounds__(256)
router_p2(int T, float* __restrict__ out, int flags) {
    const int lane  = threadIdx.x & 31;
    const int warpG = (blockIdx.x * 256 + threadIdx.x) >> 5;
    const int oct   = lane >> 3;   // which of 4 rows
    const int ol    = lane & 7;    // octet lane = warp slot / expert
    const int r     = warpG * 4 + oct;
    if (warpG * 4 >= T) return;    // full-warp guard (T % 4 == 0)

    const float4* p = reinterpret_cast<const float4*>(g_scratch + ((size_t)r * 8 + ol) * EXP);
    float4 u = p[0], v = p[1];
    float a[EXP] = {u.x, u.y, u.z, u.w, v.x, v.y, v.z, v.w};

    // octet butterfly: masks {4,2,1}; after this, octet lane e holds logit[e]
    {
        bool hi = (lane & 4) != 0;
        float s0 = hi ? a[0] : a[4];
        float s1 = hi ? a[1] : a[5];
        float s2 = hi ? a[2] : a[6];
        float s3 = hi ? a[3] : a[7];
        s0 = __shfl_xor_sync(FULLM, s0, 4);
        s1 = __shfl_xor_sync(FULLM, s1, 4);
        s2 = __shfl_xor_sync(FULLM, s2, 4);
        s3 = __shfl_xor_sync(FULLM, s3, 4);
        a[0] = (hi ? a[4] : a[0]) + s0;
        a[1] = (hi ? a[5] : a[1]) + s1;
        a[2] = (hi ? a[6] : a[2]) + s2;
        a[3] = (hi ? a[7] : a[3]) + s3;
    }
    {
        bool hi = (lane & 2) != 0;
        float s0 = hi ? a[0] : a[2];
        float s1 = hi ? a[1] : a[3];
        s0 = __shfl_xor_sync(FULLM, s0, 2);
        s1 = __shfl_xor_sync(FULLM, s1, 2);
        a[0] = (hi ? a[2] : a[0]) + s0;
        a[1] = (hi ? a[3] : a[1]) + s1;
    }
    {
        bool hi = (lane & 1) != 0;
        float s0 = hi ? a[0] : a[1];
        s0 = __shfl_xor_sync(FULLM, s0, 1);
        a[0] = (hi ? a[1] : a[0]) + s0;
    }
    float t = a[0];   // octet lane e holds logit[e] of its row

    // softmax within octet (orbit bits {2,1,0} -> masks 4,2,1)
    float m = t;
    m = fmaxf(m, __shfl_xor_sync(FULLM, m, 4));
    m = fmaxf(m, __shfl_xor_sync(FULLM, m, 2));
    m = fmaxf(m, __shfl_xor_sync(FULLM, m, 1));
    float pz = __expf(t - m);
    float sden = pz;
    sden += __shfl_xor_sync(FULLM, sden, 4);
    sden += __shfl_xor_sync(FULLM, sden, 2);
    sden += __shfl_xor_sync(FULLM, sden, 1);
    float sc = __fdividef(pz, sden);

    // broadcast all 8 scores within the octet
    float se[EXP];
#pragma unroll
    for (int j = 0; j < EXP; j++)
        se[j] = __shfl_sync(FULLM, sc, (lane & 24) | j);

    // scores: two STG.128 per row (octet lanes 0 and 1)
    if (ol < 2) {
        float4 o = ol ? make_float4(se[4], se[5], se[6], se[7])
                      : make_float4(se[0], se[1], se[2], se[3]);
        reinterpret_cast<float4*>(out + (size_t)r * EXP)[ol] = o;
    }

    // flat top-2 (ties -> lower index, matching lax.top_k)
    float v1 = se[0]; int i1 = 0;
#pragma unroll
    for (int j = 1; j < EXP; j++)
        if (se[j] > v1) { v1 = se[j]; i1 = j; }
    float v2 = -1.0f; int i2 = 0;
#pragma unroll
    for (int j = 0; j < EXP; j++)
        if (j != i1 && se[j] > v2) { v2 = se[j]; i2 = j; }

    if (ol == 2 && (flags & 1)) {
        float* outW = out + (size_t)T * EXP;
        outW[(size_t)r * 2 + 0] = v1;
        outW[(size_t)r * 2 + 1] = v2;
    }
    if (ol == 3 && (flags & 2)) {
        float* outI = out + (size_t)T * (EXP + 2);
        outI[(size_t)r * 2 + 0] = (float)i1;
        outI[(size_t)r * 2 + 1] = (float)i2;
    }
}

extern "C" void kernel_launch(void* const* d_in, const int* in_sizes, int n_in,
                              void* d_out, int out_size) {
    const float* x = (const float*)d_in[0];
    const float* W = (const float*)d_in[1];

    int T = in_sizes[0] / H;  // 16384

    int dev = 0;
    cudaGetDevice(&dev);
    int sm = 148;
    cudaDeviceGetAttribute(&sm, cudaDevAttrMultiProcessorCount, dev);

    int flags = 0;
    if (out_size >= T * (EXP + 2)) flags |= 1;
    if (out_size >= T * (EXP + 4)) flags |= 2;

    static int smemSet = 0;
    if (!smemSet) {
        cudaFuncSetAttribute(router_p1, cudaFuncAttributeMaxDynamicSharedMemorySize,
                             STAGES * ROWB);
        smemSet = 1;
    }

    router_p1<<<sm, 256, STAGES * ROWB>>>(x, W, T);
    int blocks2 = ((T / 4) * 32 + 255) / 256;   // 4 rows per warp
    router_p2<<<blocks2, 256>>>(T, (float*)d_out, flags);
}